// round 8
// baseline (speedup 1.0000x reference)
#include <cuda_runtime.h>

// ---------------------------------------------------------------------------
// Sinkhorn (Wasserstein) loss, B=16, N=M=1024, D=32, EPS=1e-3, THRESH=0.1
// Round 7: FUSED iteration — C is read exactly once per iteration.
// Thread owns 2 columns; 8-row batches: (1) block-reduce row max of (v-C),
// (2) gated exp-sum block-reduce -> u_new[row] immediately (Gauss-Seidel),
// (3) fold the same held C registers into the online column (m,s) scan.
// ---------------------------------------------------------------------------

#define BB    16
#define NN    1024
#define NBLK  288            // 18 row-chunk blocks per batch * 16 batches
#define RPB   18
#define NTHR  512
#define NWARP 16
#define CHUNK 57             // last block gets 1024-17*57=55

// EPS * log(1/1024 + 1e-8)
#define K_EPSLOGMU  (-6.9314616e-3f)
// log2(e) / EPS
#define K_L2E_EPS   (1442.6950409f)
// exp cutoff: terms below 2^-46 of the max are dropped
#define K_CUT       (-0.032f)

__device__ float  g_C[16u * 1024u * 1024u];     // C[b][i][j]
__device__ float2 g_part[2][NBLK * 1024];       // (m,s) per (block,col), parity
__device__ float  g_errpart[2][NBLK];
__device__ float  g_costpart[NBLK];
__device__ unsigned g_count;
__device__ unsigned g_release;

__device__ __forceinline__ float ex2f(float x) {
    float r;
    asm("ex2.approx.ftz.f32 %0, %1;" : "=f"(r) : "f"(x));
    return r;
}

// ---------------------------------------------------------------------------
// C[b][i][j] = sum_d (x[b][i][d] - y[b][j][d])^2 ; 32x32 output tile per block
__global__ void compute_C_kernel(const float* __restrict__ X,
                                 const float* __restrict__ Y) {
    __shared__ float xs[32][33];
    __shared__ float ys[32][33];
    int b  = blockIdx.z;
    int i0 = blockIdx.y * 32;
    int j0 = blockIdx.x * 32;
    int tid = threadIdx.x;

    if (blockIdx.x == 0 && blockIdx.y == 0 && blockIdx.z == 0 && tid == 0) {
        g_count = 0u; g_release = 0u;
    }

    const float* xp = X + ((size_t)(b * NN + i0)) * 32;
    const float* yp = Y + ((size_t)(b * NN + j0)) * 32;
    for (int idx = tid; idx < 1024; idx += 256) {
        xs[idx >> 5][idx & 31] = xp[idx];
        ys[idx >> 5][idx & 31] = yp[idx];
    }
    __syncthreads();

    int tx = tid & 31;
    int ty = tid >> 5;
    float a0 = 0.f, a1 = 0.f, a2 = 0.f, a3 = 0.f;
#pragma unroll
    for (int d = 0; d < 32; d++) {
        float yv = ys[tx][d];
        float d0 = xs[ty][d]      - yv; a0 += d0 * d0;
        float d1 = xs[ty +  8][d] - yv; a1 += d1 * d1;
        float d2 = xs[ty + 16][d] - yv; a2 += d2 * d2;
        float d3 = xs[ty + 24][d] - yv; a3 += d3 * d3;
    }
    size_t base = ((size_t)b << 20);
    g_C[base + ((size_t)(i0 + ty)      << 10) + j0 + tx] = a0;
    g_C[base + ((size_t)(i0 + ty +  8) << 10) + j0 + tx] = a1;
    g_C[base + ((size_t)(i0 + ty + 16) << 10) + j0 + tx] = a2;
    g_C[base + ((size_t)(i0 + ty + 24) << 10) + j0 + tx] = a3;
}

// ---------------------------------------------------------------------------
// Grid barrier. 288 blocks, 2 co-resident/SM guaranteed by launch_bounds(512,2)
// (regs<=64, smem ~21KB); 288 <= 296 -> single wave, no deadlock.
__device__ __forceinline__ void grid_barrier(unsigned target) {
    __syncthreads();
    if (threadIdx.x == 0) {
        __threadfence();
        if (atomicAdd(&g_count, 1u) == NBLK - 1u) {
            g_count = 0u;
            __threadfence();
            atomicAdd(&g_release, 1u);
        } else {
            while (*((volatile unsigned*)&g_release) < target) { __nanosleep(32); }
        }
        __threadfence();
    }
    __syncthreads();
}

// combine a partial (pm, ps) into running (M, S)
#define PCOMB(M, S, pm, ps) do {                                              \
    if ((pm) > (M)) {                                                         \
        float d_ = (M) - (pm);                                                \
        (S) = (S) * ((d_ >= K_CUT) ? ex2f(d_ * K_L2E_EPS) : 0.f) + (ps);      \
        (M) = (pm);                                                           \
    } else {                                                                  \
        float d_ = (pm) - (M);                                                \
        if (d_ >= K_CUT) (S) += (ps) * ex2f(d_ * K_L2E_EPS);                  \
    }                                                                         \
} while (0)

// ---------------------------------------------------------------------------
// Fused 8-row batch: u-update (block logsumexp per row) + fold into column
// online state, all on one read of C. FULL=true -> nrows==8 (no guards).
template<bool FULL>
__device__ __forceinline__ void fused_batch(
    int base, int nrows, int tid, int lane, int warp,
    float2 vv, const float2* __restrict__ Cb2,
    float* __restrict__ s_part, float* __restrict__ s_m, float* __restrict__ s_u,
    float& m0, float& s0, float& m1, float& s1, float& ei)
{
    float2 c[8];
    float  t[8];
#pragma unroll
    for (int k = 0; k < 8; k++) {
        if (FULL || k < nrows) {
            c[k] = Cb2[(size_t)(base + k) * 512 + tid];
            t[k] = fmaxf(vv.x - c[k].x, vv.y - c[k].y);
        } else {
            c[k] = make_float2(3.0e38f, 3.0e38f);
            t[k] = -3.0e38f;
        }
        s_part[k * 512 + tid] = t[k];
    }
    __syncthreads();
    if (warp < 8) {                         // warp k reduces row base+k max
        const float4* pp = (const float4*)(s_part + warp * 512);
        float4 a = pp[lane], b = pp[lane + 32], cc = pp[lane + 64], d = pp[lane + 96];
        float mm = fmaxf(fmaxf(fmaxf(fmaxf(a.x, a.y), fmaxf(a.z, a.w)),
                               fmaxf(fmaxf(b.x, b.y), fmaxf(b.z, b.w))),
                         fmaxf(fmaxf(fmaxf(cc.x, cc.y), fmaxf(cc.z, cc.w)),
                               fmaxf(fmaxf(d.x, d.y), fmaxf(d.z, d.w))));
#pragma unroll
        for (int off = 16; off; off >>= 1)
            mm = fmaxf(mm, __shfl_xor_sync(0xffffffffu, mm, off));
        if (lane == 0) s_m[warp] = mm;
    }
    __syncthreads();
#pragma unroll
    for (int k = 0; k < 8; k++) {           // gated exp contributions
        float mk = s_m[k];
        float e = 0.f;
        if ((FULL || k < nrows) && t[k] >= mk + K_CUT) {
            float x0 = vv.x - c[k].x - mk;
            float x1 = vv.y - c[k].y - mk;
            if (x0 >= K_CUT) e += ex2f(x0 * K_L2E_EPS);
            if (x1 >= K_CUT) e += ex2f(x1 * K_L2E_EPS);
        }
        s_part[k * 512 + tid] = e;
    }
    __syncthreads();
    if (warp < 8 && (FULL || warp < nrows)) {     // warp k reduces row sum
        const float4* pp = (const float4*)(s_part + warp * 512);
        float4 a = pp[lane], b = pp[lane + 32], cc = pp[lane + 64], d = pp[lane + 96];
        float ss = ((a.x + a.y) + (a.z + a.w)) + ((b.x + b.y) + (b.z + b.w))
                 + ((cc.x + cc.y) + (cc.z + cc.w)) + ((d.x + d.y) + (d.z + d.w));
#pragma unroll
        for (int off = 16; off; off >>= 1)
            ss += __shfl_xor_sync(0xffffffffu, ss, off);
        if (lane == 0) {
            float nu = K_EPSLOGMU - s_m[warp] - 1e-3f * __logf(ss);
            ei += fabsf(nu - s_u[base + warp]);
            s_u[base + warp] = nu;
        }
    }
    __syncthreads();                              // u_new visible to all

    // ---- fold batch into column online state (C regs still live) ----
    float cm0 = -3.0e38f, cm1 = -3.0e38f;
#pragma unroll
    for (int k = 0; k < 8; k++) {
        if (FULL || k < nrows) {
            float uk = s_u[base + k];             // LDS broadcast
            cm0 = fmaxf(cm0, uk - c[k].x);
            cm1 = fmaxf(cm1, uk - c[k].y);
        }
    }
    bool g = (cm0 >= m0 + K_CUT) || (cm1 >= m1 + K_CUT);
    if (__any_sync(0xffffffffu, g)) {
        float n0 = fmaxf(m0, cm0);
        float n1 = fmaxf(m1, cm1);
        s0 *= ex2f((m0 - n0) * K_L2E_EPS);        // exact 1.0 when unchanged
        s1 *= ex2f((m1 - n1) * K_L2E_EPS);
#pragma unroll
        for (int k = 0; k < 8; k++) {
            if (FULL || k < nrows) {
                float uk = s_u[base + k];
                float t0 = uk - c[k].x - n0; if (t0 >= K_CUT) s0 += ex2f(t0 * K_L2E_EPS);
                float t1 = uk - c[k].y - n1; if (t1 >= K_CUT) s1 += ex2f(t1 * K_L2E_EPS);
            }
        }
        m0 = n0; m1 = n1;
    }
}

// ---------------------------------------------------------------------------
__global__ __launch_bounds__(NTHR, 2) void sinkhorn_kernel(float* __restrict__ out) {
    __shared__ __align__(16) float s_v[1024];
    __shared__ __align__(16) float s_part[8 * 512];
    __shared__ float s_m[8];
    __shared__ float s_u[64];
    __shared__ float s_red[NWARP];
    __shared__ float s_bcast;

    int tid  = threadIdx.x;
    int lane = tid & 31;
    int warp = tid >> 5;
    int b    = blockIdx.x / RPB;
    int r    = blockIdx.x % RPB;
    int row0 = r * CHUNK;
    int cnt  = (r == RPB - 1) ? (NN - row0) : CHUNK;
    int nfull = cnt & ~7;
    const float2* Cb2 = (const float2*)(g_C + ((size_t)b << 20) + ((size_t)row0 << 10));
    const float4* sv4 = (const float4*)s_v;
    unsigned bar = 0;
    int p = 0;

    if (tid < 64) s_u[tid] = 0.f;      // u0 = 0 (syncs inside first batch)

    for (int iter = 0; iter < 100; iter++) {
        p = iter & 1;
        // ---- combine v partials (buffer p^1, written last iteration) ----
        if (iter == 0) {
            for (int j = tid; j < 1024; j += NTHR) s_v[j] = 0.f;
        } else {
            const float2* gp = g_part[p ^ 1];
            for (int j = tid; j < 1024; j += NTHR) {
                float M = -3.0e38f, S = 0.f;
#pragma unroll
                for (int rr = 0; rr < RPB; rr++) {
                    float2 q = __ldcg(&gp[(b * RPB + rr) * 1024 + j]);
                    PCOMB(M, S, q.x, q.y);
                }
                s_v[j] = K_EPSLOGMU - M - 1e-3f * __logf(S);
            }
        }
        __syncthreads();
        float2 vv = ((const float2*)s_v)[tid];

        // ---- fused sweep over the row chunk ----
        float m0 = -3.0e38f, s0 = 0.f, m1 = -3.0e38f, s1 = 0.f;
        float ei = 0.f;                 // err, accumulated on lane0 of warps 0..7
        for (int base = 0; base < nfull; base += 8)
            fused_batch<true>(base, 8, tid, lane, warp, vv, Cb2,
                              s_part, s_m, s_u, m0, s0, m1, s1, ei);
        if (nfull < cnt)
            fused_batch<false>(nfull, cnt - nfull, tid, lane, warp, vv, Cb2,
                               s_part, s_m, s_u, m0, s0, m1, s1, ei);

        // columns (2*tid, 2*tid+1) -> one float4 store into buffer p
        ((float4*)g_part[p])[blockIdx.x * 512 + tid] = make_float4(m0, s0, m1, s1);

        if (lane == 0) s_red[warp] = ei;      // warps 8..15 carry 0
        __syncthreads();
        if (warp == 0) {
            float t2 = (lane < NWARP) ? s_red[lane] : 0.f;
#pragma unroll
            for (int off = 16; off; off >>= 1)
                t2 += __shfl_xor_sync(0xffffffffu, t2, off);
            if (lane == 0) g_errpart[p][blockIdx.x] = t2;
        }

        grid_barrier(++bar);   // err parts + v partials all visible

        // total err (deterministic fixed-order sum; identical in every block)
        if (warp == 0) {
            float t2 = 0.f;
            for (int i = lane; i < NBLK; i += 32) t2 += __ldcg(&g_errpart[p][i]);
#pragma unroll
            for (int off = 16; off; off >>= 1)
                t2 += __shfl_xor_sync(0xffffffffu, t2, off);
            if (lane == 0) s_bcast = t2;
        }
        __syncthreads();
        if (s_bcast * (1.0f / 16.0f) < 0.1f) break;
    }

    // ---- final v combine (from buffer p) + transport cost ----
    {
        const float2* gp = g_part[p];
        for (int j = tid; j < 1024; j += NTHR) {
            float M = -3.0e38f, S = 0.f;
#pragma unroll
            for (int rr = 0; rr < RPB; rr++) {
                float2 q = __ldcg(&gp[(b * RPB + rr) * 1024 + j]);
                PCOMB(M, S, q.x, q.y);
            }
            s_v[j] = K_EPSLOGMU - M - 1e-3f * __logf(S);
        }
    }
    __syncthreads();

    const float* Cb = g_C + ((size_t)b << 20);
    float acc = 0.f;
    for (int idx = warp; idx < cnt; idx += NWARP) {
        float ui = s_u[idx];
        const float4* cr = (const float4*)(Cb + ((size_t)(row0 + idx) << 10));
#pragma unroll
        for (int k = 0; k < 8; k++) {
            float4 c = cr[k * 32 + lane];
            float4 v = sv4[k * 32 + lane];
            float t;
            t = ui + v.x - c.x; if (t > -0.04f) acc += ex2f(t * K_L2E_EPS) * c.x;
            t = ui + v.y - c.y; if (t > -0.04f) acc += ex2f(t * K_L2E_EPS) * c.y;
            t = ui + v.z - c.z; if (t > -0.04f) acc += ex2f(t * K_L2E_EPS) * c.z;
            t = ui + v.w - c.w; if (t > -0.04f) acc += ex2f(t * K_L2E_EPS) * c.w;
        }
    }
#pragma unroll
    for (int off = 16; off; off >>= 1)
        acc += __shfl_xor_sync(0xffffffffu, acc, off);
    if (lane == 0) s_red[warp] = acc;
    __syncthreads();
    if (warp == 0) {
        float t2 = (lane < NWARP) ? s_red[lane] : 0.f;
#pragma unroll
        for (int off = 16; off; off >>= 1)
            t2 += __shfl_xor_sync(0xffffffffu, t2, off);
        if (lane == 0) g_costpart[blockIdx.x] = t2;
    }
    grid_barrier(++bar);

    if (blockIdx.x == 0 && warp == 0) {
        float t2 = 0.f;
        for (int i = lane; i < NBLK; i += 32) t2 += __ldcg(&g_costpart[i]);
#pragma unroll
        for (int off = 16; off; off >>= 1)
            t2 += __shfl_xor_sync(0xffffffffu, t2, off);
        if (lane == 0) out[0] = t2 * (1.0f / 16.0f);
    }
}

// ---------------------------------------------------------------------------
extern "C" void kernel_launch(void* const* d_in, const int* in_sizes, int n_in,
                              void* d_out, int out_size) {
    const float* X = (const float*)d_in[0];   // output [16,1024,32]
    const float* Y = (const float*)d_in[1];   // labels [16,1024,32]

    dim3 cgrid(32, 32, 16);
    compute_C_kernel<<<cgrid, 256>>>(X, Y);

    sinkhorn_kernel<<<NBLK, NTHR>>>((float*)d_out);
}

// round 9
// speedup vs baseline: 1.0201x; 1.0201x over previous
#include <cuda_runtime.h>

// ---------------------------------------------------------------------------
// Sinkhorn (Wasserstein) loss, B=16, N=M=1024, D=32, EPS=1e-3, THRESH=0.1
// Round 7: FUSED iteration — C is read exactly once per iteration.
// Thread owns 2 columns; 8-row batches: (1) block-reduce row max of (v-C),
// (2) gated exp-sum block-reduce -> u_new[row] immediately (Gauss-Seidel),
// (3) fold the same held C registers into the online column (m,s) scan.
// ---------------------------------------------------------------------------

#define BB    16
#define NN    1024
#define NBLK  288            // 18 row-chunk blocks per batch * 16 batches
#define RPB   18
#define NTHR  512
#define NWARP 16
#define CHUNK 57             // last block gets 1024-17*57=55

// EPS * log(1/1024 + 1e-8)
#define K_EPSLOGMU  (-6.9314616e-3f)
// log2(e) / EPS
#define K_L2E_EPS   (1442.6950409f)
// exp cutoff: terms below 2^-46 of the max are dropped
#define K_CUT       (-0.032f)

__device__ float  g_C[16u * 1024u * 1024u];     // C[b][i][j]
__device__ float2 g_part[2][NBLK * 1024];       // (m,s) per (block,col), parity
__device__ float  g_errpart[2][NBLK];
__device__ float  g_costpart[NBLK];
__device__ unsigned g_count;
__device__ unsigned g_release;

__device__ __forceinline__ float ex2f(float x) {
    float r;
    asm("ex2.approx.ftz.f32 %0, %1;" : "=f"(r) : "f"(x));
    return r;
}

// ---------------------------------------------------------------------------
// C[b][i][j] = sum_d (x[b][i][d] - y[b][j][d])^2 ; 32x32 output tile per block
__global__ void compute_C_kernel(const float* __restrict__ X,
                                 const float* __restrict__ Y) {
    __shared__ float xs[32][33];
    __shared__ float ys[32][33];
    int b  = blockIdx.z;
    int i0 = blockIdx.y * 32;
    int j0 = blockIdx.x * 32;
    int tid = threadIdx.x;

    if (blockIdx.x == 0 && blockIdx.y == 0 && blockIdx.z == 0 && tid == 0) {
        g_count = 0u; g_release = 0u;
    }

    const float* xp = X + ((size_t)(b * NN + i0)) * 32;
    const float* yp = Y + ((size_t)(b * NN + j0)) * 32;
    for (int idx = tid; idx < 1024; idx += 256) {
        xs[idx >> 5][idx & 31] = xp[idx];
        ys[idx >> 5][idx & 31] = yp[idx];
    }
    __syncthreads();

    int tx = tid & 31;
    int ty = tid >> 5;
    float a0 = 0.f, a1 = 0.f, a2 = 0.f, a3 = 0.f;
#pragma unroll
    for (int d = 0; d < 32; d++) {
        float yv = ys[tx][d];
        float d0 = xs[ty][d]      - yv; a0 += d0 * d0;
        float d1 = xs[ty +  8][d] - yv; a1 += d1 * d1;
        float d2 = xs[ty + 16][d] - yv; a2 += d2 * d2;
        float d3 = xs[ty + 24][d] - yv; a3 += d3 * d3;
    }
    size_t base = ((size_t)b << 20);
    g_C[base + ((size_t)(i0 + ty)      << 10) + j0 + tx] = a0;
    g_C[base + ((size_t)(i0 + ty +  8) << 10) + j0 + tx] = a1;
    g_C[base + ((size_t)(i0 + ty + 16) << 10) + j0 + tx] = a2;
    g_C[base + ((size_t)(i0 + ty + 24) << 10) + j0 + tx] = a3;
}

// ---------------------------------------------------------------------------
// Grid barrier. 288 blocks, 2 co-resident/SM guaranteed by launch_bounds(512,2)
// (regs<=64, smem ~21KB); 288 <= 296 -> single wave, no deadlock.
__device__ __forceinline__ void grid_barrier(unsigned target) {
    __syncthreads();
    if (threadIdx.x == 0) {
        __threadfence();
        if (atomicAdd(&g_count, 1u) == NBLK - 1u) {
            g_count = 0u;
            __threadfence();
            atomicAdd(&g_release, 1u);
        } else {
            while (*((volatile unsigned*)&g_release) < target) { __nanosleep(32); }
        }
        __threadfence();
    }
    __syncthreads();
}

// combine a partial (pm, ps) into running (M, S)
#define PCOMB(M, S, pm, ps) do {                                              \
    if ((pm) > (M)) {                                                         \
        float d_ = (M) - (pm);                                                \
        (S) = (S) * ((d_ >= K_CUT) ? ex2f(d_ * K_L2E_EPS) : 0.f) + (ps);      \
        (M) = (pm);                                                           \
    } else {                                                                  \
        float d_ = (pm) - (M);                                                \
        if (d_ >= K_CUT) (S) += (ps) * ex2f(d_ * K_L2E_EPS);                  \
    }                                                                         \
} while (0)

// ---------------------------------------------------------------------------
// Fused 8-row batch: u-update (block logsumexp per row) + fold into column
// online state, all on one read of C. FULL=true -> nrows==8 (no guards).
template<bool FULL>
__device__ __forceinline__ void fused_batch(
    int base, int nrows, int tid, int lane, int warp,
    float2 vv, const float2* __restrict__ Cb2,
    float* __restrict__ s_part, float* __restrict__ s_m, float* __restrict__ s_u,
    float& m0, float& s0, float& m1, float& s1, float& ei)
{
    float2 c[8];
    float  t[8];
#pragma unroll
    for (int k = 0; k < 8; k++) {
        if (FULL || k < nrows) {
            c[k] = Cb2[(size_t)(base + k) * 512 + tid];
            t[k] = fmaxf(vv.x - c[k].x, vv.y - c[k].y);
        } else {
            c[k] = make_float2(3.0e38f, 3.0e38f);
            t[k] = -3.0e38f;
        }
        s_part[k * 512 + tid] = t[k];
    }
    __syncthreads();
    if (warp < 8) {                         // warp k reduces row base+k max
        const float4* pp = (const float4*)(s_part + warp * 512);
        float4 a = pp[lane], b = pp[lane + 32], cc = pp[lane + 64], d = pp[lane + 96];
        float mm = fmaxf(fmaxf(fmaxf(fmaxf(a.x, a.y), fmaxf(a.z, a.w)),
                               fmaxf(fmaxf(b.x, b.y), fmaxf(b.z, b.w))),
                         fmaxf(fmaxf(fmaxf(cc.x, cc.y), fmaxf(cc.z, cc.w)),
                               fmaxf(fmaxf(d.x, d.y), fmaxf(d.z, d.w))));
#pragma unroll
        for (int off = 16; off; off >>= 1)
            mm = fmaxf(mm, __shfl_xor_sync(0xffffffffu, mm, off));
        if (lane == 0) s_m[warp] = mm;
    }
    __syncthreads();
#pragma unroll
    for (int k = 0; k < 8; k++) {           // gated exp contributions
        float mk = s_m[k];
        float e = 0.f;
        if ((FULL || k < nrows) && t[k] >= mk + K_CUT) {
            float x0 = vv.x - c[k].x - mk;
            float x1 = vv.y - c[k].y - mk;
            if (x0 >= K_CUT) e += ex2f(x0 * K_L2E_EPS);
            if (x1 >= K_CUT) e += ex2f(x1 * K_L2E_EPS);
        }
        s_part[k * 512 + tid] = e;
    }
    __syncthreads();
    if (warp < 8 && (FULL || warp < nrows)) {     // warp k reduces row sum
        const float4* pp = (const float4*)(s_part + warp * 512);
        float4 a = pp[lane], b = pp[lane + 32], cc = pp[lane + 64], d = pp[lane + 96];
        float ss = ((a.x + a.y) + (a.z + a.w)) + ((b.x + b.y) + (b.z + b.w))
                 + ((cc.x + cc.y) + (cc.z + cc.w)) + ((d.x + d.y) + (d.z + d.w));
#pragma unroll
        for (int off = 16; off; off >>= 1)
            ss += __shfl_xor_sync(0xffffffffu, ss, off);
        if (lane == 0) {
            float nu = K_EPSLOGMU - s_m[warp] - 1e-3f * __logf(ss);
            ei += fabsf(nu - s_u[base + warp]);
            s_u[base + warp] = nu;
        }
    }
    __syncthreads();                              // u_new visible to all

    // ---- fold batch into column online state (C regs still live) ----
    float cm0 = -3.0e38f, cm1 = -3.0e38f;
#pragma unroll
    for (int k = 0; k < 8; k++) {
        if (FULL || k < nrows) {
            float uk = s_u[base + k];             // LDS broadcast
            cm0 = fmaxf(cm0, uk - c[k].x);
            cm1 = fmaxf(cm1, uk - c[k].y);
        }
    }
    bool g = (cm0 >= m0 + K_CUT) || (cm1 >= m1 + K_CUT);
    if (__any_sync(0xffffffffu, g)) {
        float n0 = fmaxf(m0, cm0);
        float n1 = fmaxf(m1, cm1);
        s0 *= ex2f((m0 - n0) * K_L2E_EPS);        // exact 1.0 when unchanged
        s1 *= ex2f((m1 - n1) * K_L2E_EPS);
#pragma unroll
        for (int k = 0; k < 8; k++) {
            if (FULL || k < nrows) {
                float uk = s_u[base + k];
                float t0 = uk - c[k].x - n0; if (t0 >= K_CUT) s0 += ex2f(t0 * K_L2E_EPS);
                float t1 = uk - c[k].y - n1; if (t1 >= K_CUT) s1 += ex2f(t1 * K_L2E_EPS);
            }
        }
        m0 = n0; m1 = n1;
    }
}

// ---------------------------------------------------------------------------
__global__ __launch_bounds__(NTHR, 2) void sinkhorn_kernel(float* __restrict__ out) {
    __shared__ __align__(16) float s_v[1024];
    __shared__ __align__(16) float s_part[8 * 512];
    __shared__ float s_m[8];
    __shared__ float s_u[64];
    __shared__ float s_red[NWARP];
    __shared__ float s_bcast;

    int tid  = threadIdx.x;
    int lane = tid & 31;
    int warp = tid >> 5;
    int b    = blockIdx.x / RPB;
    int r    = blockIdx.x % RPB;
    int row0 = r * CHUNK;
    int cnt  = (r == RPB - 1) ? (NN - row0) : CHUNK;
    int nfull = cnt & ~7;
    const float2* Cb2 = (const float2*)(g_C + ((size_t)b << 20) + ((size_t)row0 << 10));
    const float4* sv4 = (const float4*)s_v;
    unsigned bar = 0;
    int p = 0;

    if (tid < 64) s_u[tid] = 0.f;      // u0 = 0 (syncs inside first batch)

    for (int iter = 0; iter < 100; iter++) {
        p = iter & 1;
        // ---- combine v partials (buffer p^1, written last iteration) ----
        if (iter == 0) {
            for (int j = tid; j < 1024; j += NTHR) s_v[j] = 0.f;
        } else {
            const float2* gp = g_part[p ^ 1];
            for (int j = tid; j < 1024; j += NTHR) {
                float M = -3.0e38f, S = 0.f;
#pragma unroll
                for (int rr = 0; rr < RPB; rr++) {
                    float2 q = __ldcg(&gp[(b * RPB + rr) * 1024 + j]);
                    PCOMB(M, S, q.x, q.y);
                }
                s_v[j] = K_EPSLOGMU - M - 1e-3f * __logf(S);
            }
        }
        __syncthreads();
        float2 vv = ((const float2*)s_v)[tid];

        // ---- fused sweep over the row chunk ----
        float m0 = -3.0e38f, s0 = 0.f, m1 = -3.0e38f, s1 = 0.f;
        float ei = 0.f;                 // err, accumulated on lane0 of warps 0..7
        for (int base = 0; base < nfull; base += 8)
            fused_batch<true>(base, 8, tid, lane, warp, vv, Cb2,
                              s_part, s_m, s_u, m0, s0, m1, s1, ei);
        if (nfull < cnt)
            fused_batch<false>(nfull, cnt - nfull, tid, lane, warp, vv, Cb2,
                               s_part, s_m, s_u, m0, s0, m1, s1, ei);

        // columns (2*tid, 2*tid+1) -> one float4 store into buffer p
        ((float4*)g_part[p])[blockIdx.x * 512 + tid] = make_float4(m0, s0, m1, s1);

        if (lane == 0) s_red[warp] = ei;      // warps 8..15 carry 0
        __syncthreads();
        if (warp == 0) {
            float t2 = (lane < NWARP) ? s_red[lane] : 0.f;
#pragma unroll
            for (int off = 16; off; off >>= 1)
                t2 += __shfl_xor_sync(0xffffffffu, t2, off);
            if (lane == 0) g_errpart[p][blockIdx.x] = t2;
        }

        grid_barrier(++bar);   // err parts + v partials all visible

        // total err (deterministic fixed-order sum; identical in every block)
        if (warp == 0) {
            float t2 = 0.f;
            for (int i = lane; i < NBLK; i += 32) t2 += __ldcg(&g_errpart[p][i]);
#pragma unroll
            for (int off = 16; off; off >>= 1)
                t2 += __shfl_xor_sync(0xffffffffu, t2, off);
            if (lane == 0) s_bcast = t2;
        }
        __syncthreads();
        if (s_bcast * (1.0f / 16.0f) < 0.1f) break;
    }

    // ---- final v combine (from buffer p) + transport cost ----
    {
        const float2* gp = g_part[p];
        for (int j = tid; j < 1024; j += NTHR) {
            float M = -3.0e38f, S = 0.f;
#pragma unroll
            for (int rr = 0; rr < RPB; rr++) {
                float2 q = __ldcg(&gp[(b * RPB + rr) * 1024 + j]);
                PCOMB(M, S, q.x, q.y);
            }
            s_v[j] = K_EPSLOGMU - M - 1e-3f * __logf(S);
        }
    }
    __syncthreads();

    const float* Cb = g_C + ((size_t)b << 20);
    float acc = 0.f;
    for (int idx = warp; idx < cnt; idx += NWARP) {
        float ui = s_u[idx];
        const float4* cr = (const float4*)(Cb + ((size_t)(row0 + idx) << 10));
#pragma unroll
        for (int k = 0; k < 8; k++) {
            float4 c = cr[k * 32 + lane];
            float4 v = sv4[k * 32 + lane];
            float t;
            t = ui + v.x - c.x; if (t > -0.04f) acc += ex2f(t * K_L2E_EPS) * c.x;
            t = ui + v.y - c.y; if (t > -0.04f) acc += ex2f(t * K_L2E_EPS) * c.y;
            t = ui + v.z - c.z; if (t > -0.04f) acc += ex2f(t * K_L2E_EPS) * c.z;
            t = ui + v.w - c.w; if (t > -0.04f) acc += ex2f(t * K_L2E_EPS) * c.w;
        }
    }
#pragma unroll
    for (int off = 16; off; off >>= 1)
        acc += __shfl_xor_sync(0xffffffffu, acc, off);
    if (lane == 0) s_red[warp] = acc;
    __syncthreads();
    if (warp == 0) {
        float t2 = (lane < NWARP) ? s_red[lane] : 0.f;
#pragma unroll
        for (int off = 16; off; off >>= 1)
            t2 += __shfl_xor_sync(0xffffffffu, t2, off);
        if (lane == 0) g_costpart[blockIdx.x] = t2;
    }
    grid_barrier(++bar);

    if (blockIdx.x == 0 && warp == 0) {
        float t2 = 0.f;
        for (int i = lane; i < NBLK; i += 32) t2 += __ldcg(&g_costpart[i]);
#pragma unroll
        for (int off = 16; off; off >>= 1)
            t2 += __shfl_xor_sync(0xffffffffu, t2, off);
        if (lane == 0) out[0] = t2 * (1.0f / 16.0f);
    }
}

// ---------------------------------------------------------------------------
extern "C" void kernel_launch(void* const* d_in, const int* in_sizes, int n_in,
                              void* d_out, int out_size) {
    const float* X = (const float*)d_in[0];   // output [16,1024,32]
    const float* Y = (const float*)d_in[1];   // labels [16,1024,32]

    dim3 cgrid(32, 32, 16);
    compute_C_kernel<<<cgrid, 256>>>(X, Y);

    sinkhorn_kernel<<<NBLK, NTHR>>>((float*)d_out);
}